// round 14
// baseline (speedup 1.0000x reference)
#include <cuda_runtime.h>
#include <cuda_fp16.h>
#include <cuda_pipeline.h>
#include <cstdint>

#define BB 4
#define LQ 256
#define LK 256
#define DD 768

// Scratch (no cudaMalloc allowed)
__device__ __half g_qh[BB*LQ*DD];        // q projection (fp16, feeds score)
__device__ __half g_kh[BB*LK*DD];        // k projection (fp16, feeds score)
__device__ __half g_vh[BB*LK*DD];        // v projection (fp16, feeds av)
__device__ __half g_xh[3][BB*LQ*DD];     // fp16 copies of query,key,value inputs
__device__ __half g_wh[3][DD*DD];        // fp16 copies of Wq,Wk,Wv
__device__ float  g_scores[BB*LQ*LK];
__device__ float2 g_tab[2048];           // tanh LUT: (value, secant-slope per h)

// ---- f16x2 helpers ----
__device__ __forceinline__ uint32_t hadd2u(uint32_t a, uint32_t b) {
    uint32_t r;
    asm("add.rn.f16x2 %0, %1, %2;" : "=r"(r) : "r"(a), "r"(b));
    return r;
}
__device__ __forceinline__ uint32_t tanh2u(uint32_t a) {
    uint32_t r;
    asm("tanh.approx.f16x2 %0, %1;" : "=r"(r) : "r"(a));
    return r;
}
__device__ __forceinline__ uint32_t hfma2u(uint32_t a, uint32_t b, uint32_t c) {
    uint32_t r;
    asm("fma.rn.f16x2 %0, %1, %2, %3;" : "=r"(r) : "r"(a), "r"(b), "r"(c));
    return r;
}
__device__ __forceinline__ float2 h22f2(uint32_t h) {
    __half2 hh = *(__half2*)&h;
    return __half22float2(hh);
}

// ---- fp16 mma helpers ----
__device__ __forceinline__ void mma_f16(float& d0, float& d1, float& d2, float& d3,
                                        uint32_t a0, uint32_t a1, uint32_t a2, uint32_t a3,
                                        uint32_t b0, uint32_t b1) {
    asm("mma.sync.aligned.m16n8k16.row.col.f32.f16.f16.f32 "
        "{%0,%1,%2,%3}, {%4,%5,%6,%7}, {%8,%9}, {%0,%1,%2,%3};"
        : "+f"(d0), "+f"(d1), "+f"(d2), "+f"(d3)
        : "r"(a0), "r"(a1), "r"(a2), "r"(a3), "r"(b0), "r"(b1));
}
__device__ __forceinline__ void ldsm_x4(uint32_t& r0, uint32_t& r1, uint32_t& r2, uint32_t& r3,
                                        uint32_t addr) {
    asm volatile("ldmatrix.sync.aligned.m8n8.x4.shared.b16 {%0,%1,%2,%3}, [%4];"
                 : "=r"(r0), "=r"(r1), "=r"(r2), "=r"(r3) : "r"(addr));
}
__device__ __forceinline__ void ldsm_x4_t(uint32_t& r0, uint32_t& r1, uint32_t& r2, uint32_t& r3,
                                          uint32_t addr) {
    asm volatile("ldmatrix.sync.aligned.m8n8.x4.trans.shared.b16 {%0,%1,%2,%3}, [%4];"
                 : "=r"(r0), "=r"(r1), "=r"(r2), "=r"(r3) : "r"(addr));
}

// ---------------------------------------------------------------------------
// Convert the 6 fp32 operand arrays to fp16 + build tanh LUT. Grid (384,7).
// ---------------------------------------------------------------------------
__global__ __launch_bounds__(256) void cvt_kernel(
    const float* __restrict__ xq, const float* __restrict__ xk, const float* __restrict__ xv,
    const float* __restrict__ Wq, const float* __restrict__ Wk, const float* __restrict__ Wv)
{
    const int id = blockIdx.y;
    if (id == 6) {
        // tanh LUT: 2048 entries over [-16,16), h = 1/64
        const int i = blockIdx.x * 256 + threadIdx.x;
        if (i < 2048) {
            const float x = (i - 1024) * 0.015625f;
            const float v = tanhf(x);
            const float s = tanhf(x + 0.0078125f) - tanhf(x - 0.0078125f);
            g_tab[i] = make_float2(v, s);
        }
        return;
    }
    const float* src;
    __half* dst;
    int n;
    if (id < 3) {
        src = (id == 0) ? xq : (id == 1) ? xk : xv;
        dst = g_xh[id];
        n = BB * LQ * DD;
    } else {
        src = (id == 3) ? Wq : (id == 4) ? Wk : Wv;
        dst = g_wh[id - 3];
        n = DD * DD;
    }
    const int idx = (blockIdx.x * 256 + threadIdx.x) * 8;
    if (idx >= n) return;
    float4 a = *(const float4*)(src + idx);
    float4 b = *(const float4*)(src + idx + 4);
    __half2 h0 = __floats2half2_rn(a.x, a.y);
    __half2 h1 = __floats2half2_rn(a.z, a.w);
    __half2 h2 = __floats2half2_rn(b.x, b.y);
    __half2 h3 = __floats2half2_rn(b.z, b.w);
    uint4 o;
    o.x = *(const uint32_t*)&h0;
    o.y = *(const uint32_t*)&h1;
    o.z = *(const uint32_t*)&h2;
    o.w = *(const uint32_t*)&h3;
    *(uint4*)(dst + idx) = o;
}

// ---------------------------------------------------------------------------
// Projection GEMM via fp16 mma (unchanged from R13, passing at ~25us).
// ---------------------------------------------------------------------------
__global__ __launch_bounds__(256) void proj_kernel(
    const float* __restrict__ bq, const float* __restrict__ bk, const float* __restrict__ bv)
{
    const int z = blockIdx.z;
    const __half* X = g_xh[z];
    const __half* W = g_wh[z];
    const float* bias = (z == 0) ? bq : (z == 1) ? bk : bv;
    __half* Out = (z == 0) ? g_qh : (z == 1) ? g_kh : g_vh;

    __shared__ __half As[2][64][40];
    __shared__ __half Bsm[2][32][136];

    const int t    = threadIdx.x;
    const int wid  = t >> 5;
    const int lane = t & 31;
    const int wm   = wid & 1;
    const int wn   = wid >> 1;
    const int grp  = lane >> 2;
    const int tig  = lane & 3;

    const int m0 = blockIdx.y * 64;
    const int n0 = blockIdx.x * 128;

    float acc[2][4][4];
    #pragma unroll
    for (int i = 0; i < 2; i++)
        #pragma unroll
        for (int j = 0; j < 4; j++)
            #pragma unroll
            for (int r = 0; r < 4; r++) acc[i][j][r] = 0.f;

    const int ar = t >> 2, acs = (t & 3) * 8;
    const int br = t >> 3, bcs = (t & 7) * 16;

    const __half* Xp = X + (size_t)(m0 + ar) * DD + acs;
    const __half* Wp = W + (size_t)br * DD + n0 + bcs;

    const int lrow = lane & 15;
    const int lca  = (lane >> 4) * 8;
    const uint32_t a_addr0 =
        (uint32_t)__cvta_generic_to_shared(&As[0][wm*32 + lrow][lca]);
    const int brow = ((lane >> 3) & 1) * 8 + (lane & 7);
    const int bcol = (lane >> 4) * 8;
    const uint32_t b_addr0 =
        (uint32_t)__cvta_generic_to_shared(&Bsm[0][brow][wn*32 + bcol]);

    __pipeline_memcpy_async(&As[0][ar][acs], Xp, 16);
    __pipeline_memcpy_async(&Bsm[0][br][bcs],     Wp,     16);
    __pipeline_memcpy_async(&Bsm[0][br][bcs + 8], Wp + 8, 16);
    __pipeline_commit();

    for (int k0 = 0; k0 < DD; k0 += 32) {
        const int buf = (k0 >> 5) & 1;
        if (k0 + 32 < DD) {
            const int nb = buf ^ 1;
            __pipeline_memcpy_async(&As[nb][ar][acs], Xp + k0 + 32, 16);
            const __half* wpn = Wp + (size_t)(k0 + 32) * DD;
            __pipeline_memcpy_async(&Bsm[nb][br][bcs],     wpn,     16);
            __pipeline_memcpy_async(&Bsm[nb][br][bcs + 8], wpn + 8, 16);
            __pipeline_commit();
            __pipeline_wait_prior(1);
        } else {
            __pipeline_wait_prior(0);
        }
        __syncthreads();

        #pragma unroll
        for (int ks = 0; ks < 2; ks++) {
            uint32_t a[2][4];
            #pragma unroll
            for (int mi = 0; mi < 2; mi++) {
                const uint32_t ad = a_addr0 + (uint32_t)(buf*5120 + mi*1280 + ks*32);
                ldsm_x4(a[mi][0], a[mi][1], a[mi][2], a[mi][3], ad);
            }
            uint32_t b[4][2];
            #pragma unroll
            for (int p = 0; p < 2; p++) {
                const uint32_t bd = b_addr0 + (uint32_t)(buf*8704 + ks*4352 + p*32);
                ldsm_x4_t(b[p*2][0], b[p*2][1], b[p*2+1][0], b[p*2+1][1], bd);
            }
            #pragma unroll
            for (int mi = 0; mi < 2; mi++)
                #pragma unroll
                for (int ni = 0; ni < 4; ni++)
                    mma_f16(acc[mi][ni][0], acc[mi][ni][1], acc[mi][ni][2], acc[mi][ni][3],
                            a[mi][0], a[mi][1], a[mi][2], a[mi][3],
                            b[ni][0], b[ni][1]);
        }
        __syncthreads();
    }

    #pragma unroll
    for (int mi = 0; mi < 2; mi++) {
        #pragma unroll
        for (int ni = 0; ni < 4; ni++) {
            const int col = n0 + wn*32 + ni*8 + 2*tig;
            const float b0 = bias[col], b1 = bias[col+1];
            const int r0 = m0 + wm*32 + mi*16 + grp;
            const int r1 = r0 + 8;
            __half2 lo = __floats2half2_rn(acc[mi][ni][0] + b0, acc[mi][ni][1] + b1);
            __half2 hi = __floats2half2_rn(acc[mi][ni][2] + b0, acc[mi][ni][3] + b1);
            *(__half2*)&Out[(size_t)r0 * DD + col] = lo;
            *(__half2*)&Out[(size_t)r1 * DD + col] = hi;
        }
    }
}

// ---------------------------------------------------------------------------
// Scores, hybrid-pipe: per 64-d chunk, d 0..39 via tanh.approx.f16x2 (MUFU),
// d 40..63 via smem LUT + linear interp (FMA/ALU/LDS pipes). This splits the
// tanh work across pipes instead of hitting the MUFU wall (~43us).
// 32x32 tile, 256 thr, 2x2 micro. Grid (8,8,4).
// ---------------------------------------------------------------------------
#define MAGICF 12582912.0f   // 1.5 * 2^23
__global__ __launch_bounds__(256) void score_kernel(const float* __restrict__ Ws,
                                                    const float* __restrict__ bsp)
{
    const int bz = blockIdx.z;
    const int q0 = blockIdx.y * 32;
    const int k0 = blockIdx.x * 32;

    __shared__ float2   Tab[2048];      // 16KB tanh LUT
    __shared__ uint32_t Qh[32][20];     // d-pairs 0..19 (d 0..39), half2
    __shared__ uint32_t Kt[20][33];     // transposed half2
    __shared__ float    Qf[32][28];     // d 40..63 as f32 (24 cols)
    __shared__ float    Ktf[24][33];    // transposed f32
    __shared__ uint32_t Wsh[20];        // Ws half2 (d 0..39)
    __shared__ float    Wsf[24];        // Ws f32 (d 40..63)

    const int t  = threadIdx.x;
    const int tx = t & 15, ty = t >> 4;

    // stage LUT into smem (4 passes x 16B/thread)
    #pragma unroll
    for (int p = 0; p < 4; p++)
        __pipeline_memcpy_async(&Tab[p*512 + t*2], &g_tab[p*512 + t*2], 16);
    __pipeline_commit();
    __pipeline_wait_prior(0);

    float acc00 = 0.f, acc01 = 0.f, acc10 = 0.f, acc11 = 0.f;

    const __half* qb = g_qh + ((size_t)bz*LQ + q0) * DD;
    const __half* kb = g_kh + ((size_t)bz*LK + k0) * DD;

    const int lr = t >> 3;          // 0..31
    const int lc = t & 7;           // 0..7  (8 halves = 16B per thread)

    for (int d0 = 0; d0 < DD; d0 += 64) {
        uint4 qv = *(const uint4*)(qb + (size_t)lr*DD + d0 + lc*8);
        uint4 kv = *(const uint4*)(kb + (size_t)lr*DD + d0 + lc*8);
        if (lc < 5) {
            // MUFU region: cols 0..39 -> half2 pairs
            *(uint4*)&Qh[lr][lc*4] = qv;
            Kt[lc*4+0][lr] = kv.x;
            Kt[lc*4+1][lr] = kv.y;
            Kt[lc*4+2][lr] = kv.z;
            Kt[lc*4+3][lr] = kv.w;
        } else {
            // LUT region: cols 40..63 -> f32
            const int c = (lc - 5) * 8;
            float2 q0f = h22f2(qv.x), q1f = h22f2(qv.y);
            float2 q2f = h22f2(qv.z), q3f = h22f2(qv.w);
            Qf[lr][c+0] = q0f.x; Qf[lr][c+1] = q0f.y;
            Qf[lr][c+2] = q1f.x; Qf[lr][c+3] = q1f.y;
            Qf[lr][c+4] = q2f.x; Qf[lr][c+5] = q2f.y;
            Qf[lr][c+6] = q3f.x; Qf[lr][c+7] = q3f.y;
            float2 k0f = h22f2(kv.x), k1f = h22f2(kv.y);
            float2 k2f = h22f2(kv.z), k3f = h22f2(kv.w);
            Ktf[c+0][lr] = k0f.x; Ktf[c+1][lr] = k0f.y;
            Ktf[c+2][lr] = k1f.x; Ktf[c+3][lr] = k1f.y;
            Ktf[c+4][lr] = k2f.x; Ktf[c+5][lr] = k2f.y;
            Ktf[c+6][lr] = k3f.x; Ktf[c+7][lr] = k3f.y;
        }
        if (t < 20) {
            float2 w = *(const float2*)&Ws[d0 + t*2];
            __half2 wh = __floats2half2_rn(w.x, w.y);
            Wsh[t] = *(const uint32_t*)&wh;
        }
        if (t >= 64 && t < 88) {
            Wsf[t - 64] = Ws[d0 + 40 + (t - 64)];
        }
        __syncthreads();

        // ---- MUFU part: 20 d-pairs (d 0..39), fp16 partials flushed per 4 ----
        #pragma unroll
        for (int g = 0; g < 5; g++) {
            uint32_t p00 = 0u, p01 = 0u, p10 = 0u, p11 = 0u;
            #pragma unroll
            for (int u = 0; u < 4; u++) {
                const int dp = g*4 + u;
                const uint32_t w2 = Wsh[dp];
                const uint32_t qa = Qh[ty*2+0][dp];
                const uint32_t qc = Qh[ty*2+1][dp];
                const uint32_t ka = Kt[dp][tx*2+0];
                const uint32_t kc = Kt[dp][tx*2+1];
                p00 = hfma2u(w2, tanh2u(hadd2u(qa, ka)), p00);
                p01 = hfma2u(w2, tanh2u(hadd2u(qa, kc)), p01);
                p10 = hfma2u(w2, tanh2u(hadd2u(qc, ka)), p10);
                p11 = hfma2u(w2, tanh2u(hadd2u(qc, kc)), p11);
            }
            float2 f0 = h22f2(p00); acc00 += f0.x + f0.y;
            float2 f1 = h22f2(p01); acc01 += f1.x + f1.y;
            float2 f2 = h22f2(p10); acc10 += f2.x + f2.y;
            float2 f3 = h22f2(p11); acc11 += f3.x + f3.y;
        }

        // ---- LUT part: d 40..63 (24 values), f32 interp on FMA/ALU/LDS ----
        #pragma unroll 8
        for (int d = 0; d < 24; d++) {
            const float w  = Wsf[d];
            const float qa = Qf[ty*2+0][d];
            const float qc = Qf[ty*2+1][d];
            const float ka = Ktf[d][tx*2+0];
            const float kc = Ktf[d][tx*2+1];
            #pragma unroll
            for (int e = 0; e < 4; e++) {
                const float x0 = (e < 2) ? qa : qc;
                const float x1 = (e & 1) ? kc : ka;
                float x = x0 + x1;
                x = fminf(fmaxf(x, -15.9f), 15.9f);
                const float y  = fmaf(x, 64.0f, MAGICF);
                const int  idx = (int)__float_as_uint(y) + (1024 - 0x4B400000);
                const float fl = y - MAGICF;
                const float fr = fmaf(x, 64.0f, -fl);
                const float2 ts = Tab[idx];
                const float tv = fmaf(fr, ts.y, ts.x);
                if (e == 0)      acc00 = fmaf(w, tv, acc00);
                else if (e == 1) acc01 = fmaf(w, tv, acc01);
                else if (e == 2) acc10 = fmaf(w, tv, acc10);
                else             acc11 = fmaf(w, tv, acc11);
            }
        }
        __syncthreads();
    }

    const float bsv = *bsp;
    float* sp = g_scores + ((size_t)bz*LQ + q0) * LK + k0;
    sp[(ty*2+0)*LK + tx*2+0] = acc00 + bsv;
    sp[(ty*2+0)*LK + tx*2+1] = acc01 + bsv;
    sp[(ty*2+1)*LK + tx*2+0] = acc10 + bsv;
    sp[(ty*2+1)*LK + tx*2+1] = acc11 + bsv;
}

// ---------------------------------------------------------------------------
// Row softmax over LK=256. One block (256 threads) per (b,q) row.
// ---------------------------------------------------------------------------
__global__ __launch_bounds__(256) void softmax_kernel(float* __restrict__ wout)
{
    const int row = blockIdx.x;
    const int t   = threadIdx.x;
    __shared__ float red[8];

    const float v = g_scores[(size_t)row*LK + t];

    float m = v;
    #pragma unroll
    for (int o = 16; o > 0; o >>= 1) m = fmaxf(m, __shfl_xor_sync(0xffffffffu, m, o));
    if ((t & 31) == 0) red[t >> 5] = m;
    __syncthreads();
    float mx = red[0];
    #pragma unroll
    for (int i = 1; i < 8; i++) mx = fmaxf(mx, red[i]);
    __syncthreads();

    const float e = __expf(v - mx);
    float s = e;
    #pragma unroll
    for (int o = 16; o > 0; o >>= 1) s += __shfl_xor_sync(0xffffffffu, s, o);
    if ((t & 31) == 0) red[t >> 5] = s;
    __syncthreads();
    float sum = 0.f;
    #pragma unroll
    for (int i = 0; i < 8; i++) sum += red[i];

    wout[(size_t)row*LK + t] = e * (1.0f / sum);
}

// ---------------------------------------------------------------------------
// attended = weights @ v via fp16 mma (unchanged from R13, ~13us).
// ---------------------------------------------------------------------------
__global__ __launch_bounds__(256) void av_kernel(const float* __restrict__ wts,
                                                 float* __restrict__ out)
{
    const int b  = blockIdx.z;
    const int q0 = blockIdx.y * 32;
    const int d0 = blockIdx.x * 128;

    __shared__ __half As[2][32][40];
    __shared__ __half Bsm[2][32][136];

    const int t    = threadIdx.x;
    const int wid  = t >> 5;
    const int lane = t & 31;
    const int grp  = lane >> 2;
    const int tig  = lane & 3;

    float acc[2][2][4];
    #pragma unroll
    for (int i = 0; i < 2; i++)
        #pragma unroll
        for (int j = 0; j < 2; j++)
            #pragma unroll
            for (int r = 0; r < 4; r++) acc[i][j][r] = 0.f;

    const int ar = t >> 3, ac4 = (t & 7) * 4;
    const int br = t >> 3, bcs = (t & 7) * 16;

    const float*  Ap = wts + ((size_t)b*LQ + q0 + ar) * LK + ac4;
    const __half* Bp = g_vh + ((size_t)b*LK + br) * DD + d0 + bcs;

    const int lrow = lane & 15;
    const int lca  = (lane >> 4) * 8;
    const uint32_t a_addr0 = (uint32_t)__cvta_generic_to_shared(&As[0][lrow][lca]);
    const int brow = ((lane >> 3) & 1) * 8 + (lane & 7);
    const int bcol = (lane >> 4) * 8;
    const uint32_t b_addr0 =
        (uint32_t)__cvta_generic_to_shared(&Bsm[0][brow][wid*16 + bcol]);

    float4 pa = *(const float4*)(Ap);
    __pipeline_memcpy_async(&Bsm[0][br][bcs],     Bp,     16);
    __pipeline_memcpy_async(&Bsm[0][br][bcs + 8], Bp + 8, 16);
    __pipeline_commit();

    for (int j0 = 0; j0 < LK; j0 += 32) {
        const int buf = (j0 >> 5) & 1;
        {
            __half2 h0 = __floats2half2_rn(pa.x, pa.y);
            __half2 h1 = __floats2half2_rn(pa.z, pa.w);
            uint2 o = { *(const uint32_t*)&h0, *(const uint32_t*)&h1 };
            *(uint2*)&As[buf][ar][ac4] = o;
        }
        if (j0 + 32 < LK) {
            const int nb = buf ^ 1;
            pa = *(const float4*)(Ap + j0 + 32);
            const __half* bpn = Bp + (size_t)(j0 + 32) * DD;
            __pipeline_memcpy_async(&Bsm[nb][br][bcs],     bpn,     16);
            __pipeline_memcpy_async(&Bsm[nb][br][bcs + 8], bpn + 8, 16);
            __pipeline_commit();
            __pipeline_wait_prior(1);
        } else {
            __pipeline_wait_prior(0);
        }
        __syncthreads();

        #pragma unroll
        for (int ks = 0; ks < 2; ks++) {
            uint32_t a[2][4];
            #pragma unroll
            for (int mi = 0; mi < 2; mi++) {
                const uint32_t ad = a_addr0 + (uint32_t)(buf*2560 + mi*1280 + ks*32);
                ldsm_x4(a[mi][0], a[mi][1], a[mi][2], a[mi][3], ad);
            }
            uint32_t bf[2][2];
            {
                const uint32_t bd = b_addr0 + (uint32_t)(buf*8704 + ks*4352);
                ldsm_x4_t(bf[0][0], bf[0][1], bf[1][0], bf[1][1], bd);
            }
            #pragma unroll
            for (int mi = 0; mi < 2; mi++)
                #pragma unroll
                for (int ni = 0; ni < 2; ni++)
                    mma_f16(acc[mi][ni][0], acc[mi][ni][1], acc[mi][ni][2], acc[mi][ni][3],
                            a[mi][0], a[mi][1], a[mi][2], a[mi][3],
                            bf[ni][0], bf[ni][1]);
        }
        __syncthreads();
    }

    #pragma unroll
    for (int mi = 0; mi < 2; mi++) {
        #pragma unroll
        for (int ni = 0; ni < 2; ni++) {
            const int col = d0 + wid*16 + ni*8 + 2*tig;
            const int r0  = q0 + mi*16 + grp;
            const int r1  = r0 + 8;
            float2 lo = { acc[mi][ni][0], acc[mi][ni][1] };
            float2 hi = { acc[mi][ni][2], acc[mi][ni][3] };
            *(float2*)&out[((size_t)b*LQ + r0) * DD + col] = lo;
            *(float2*)&out[((size_t)b*LQ + r1) * DD + col] = hi;
        }
    }
}

// ---------------------------------------------------------------------------
extern "C" void kernel_launch(void* const* d_in, const int* in_sizes, int n_in,
                              void* d_out, int out_size)
{
    const float* query = (const float*)d_in[0];
    const float* key   = (const float*)d_in[1];
    const float* value = (const float*)d_in[2];
    const float* Wq    = (const float*)d_in[3];
    const float* bq    = (const float*)d_in[4];
    const float* Wk    = (const float*)d_in[5];
    const float* bk    = (const float*)d_in[6];
    const float* Wv    = (const float*)d_in[7];
    const float* bv    = (const float*)d_in[8];
    const float* Ws    = (const float*)d_in[9];
    const float* bs    = (const float*)d_in[10];

    float* att = (float*)d_out;                  // [B,LQ,D]
    float* wts = att + (size_t)BB * LQ * DD;     // [B,LQ,LK]

    // 0) fp32 -> fp16 operand conversion + tanh LUT build (once)
    cvt_kernel<<<dim3(384, 7), 256>>>(query, key, value, Wq, Wk, Wv);

    // 1) q,k,v projections (fp16 mma; all outputs fp16)
    proj_kernel<<<dim3(DD/128, (BB*LQ)/64, 3), 256>>>(bq, bk, bv);

    // 2) additive scores (hybrid MUFU f16x2 + smem-LUT pipes)
    score_kernel<<<dim3(LK/32, LQ/32, BB), 256>>>(Ws, bs);

    // 3) softmax -> attention_weights into d_out
    softmax_kernel<<<BB*LQ, 256>>>(wts);

    // 4) attended = weights @ v (fp16 mma)
    av_kernel<<<dim3(DD/128, LQ/32, BB), 256>>>(wts, att);
}

// round 15
// speedup vs baseline: 1.0006x; 1.0006x over previous
#include <cuda_runtime.h>
#include <cuda_fp16.h>
#include <cuda_pipeline.h>
#include <cstdint>

#define BB 4
#define LQ 256
#define LK 256
#define DD 768

// Scratch (no cudaMalloc allowed)
__device__ __half g_qh[BB*LQ*DD];        // q projection (fp16, feeds score)
__device__ __half g_kh[BB*LK*DD];        // k projection (fp16, feeds score)
__device__ __half g_vh[BB*LK*DD];        // v projection (fp16, feeds av)
__device__ __half g_xh[3][BB*LQ*DD];     // fp16 copies of query,key,value inputs
__device__ __half g_wh[3][DD*DD];        // fp16 copies of Wq,Wk,Wv
__device__ float  g_scores[BB*LQ*LK];

// ---- f16x2 helpers ----
__device__ __forceinline__ uint32_t hadd2u(uint32_t a, uint32_t b) {
    uint32_t r;
    asm("add.rn.f16x2 %0, %1, %2;" : "=r"(r) : "r"(a), "r"(b));
    return r;
}
__device__ __forceinline__ uint32_t tanh2u(uint32_t a) {
    uint32_t r;
    asm("tanh.approx.f16x2 %0, %1;" : "=r"(r) : "r"(a));
    return r;
}
__device__ __forceinline__ uint32_t hfma2u(uint32_t a, uint32_t b, uint32_t c) {
    uint32_t r;
    asm("fma.rn.f16x2 %0, %1, %2, %3;" : "=r"(r) : "r"(a), "r"(b), "r"(c));
    return r;
}
__device__ __forceinline__ float2 h22f2(uint32_t h) {
    __half2 hh = *(__half2*)&h;
    return __half22float2(hh);
}

// ---- fp16 mma helpers ----
__device__ __forceinline__ void mma_f16(float& d0, float& d1, float& d2, float& d3,
                                        uint32_t a0, uint32_t a1, uint32_t a2, uint32_t a3,
                                        uint32_t b0, uint32_t b1) {
    asm("mma.sync.aligned.m16n8k16.row.col.f32.f16.f16.f32 "
        "{%0,%1,%2,%3}, {%4,%5,%6,%7}, {%8,%9}, {%0,%1,%2,%3};"
        : "+f"(d0), "+f"(d1), "+f"(d2), "+f"(d3)
        : "r"(a0), "r"(a1), "r"(a2), "r"(a3), "r"(b0), "r"(b1));
}
__device__ __forceinline__ void ldsm_x4(uint32_t& r0, uint32_t& r1, uint32_t& r2, uint32_t& r3,
                                        uint32_t addr) {
    asm volatile("ldmatrix.sync.aligned.m8n8.x4.shared.b16 {%0,%1,%2,%3}, [%4];"
                 : "=r"(r0), "=r"(r1), "=r"(r2), "=r"(r3) : "r"(addr));
}
__device__ __forceinline__ void ldsm_x4_t(uint32_t& r0, uint32_t& r1, uint32_t& r2, uint32_t& r3,
                                          uint32_t addr) {
    asm volatile("ldmatrix.sync.aligned.m8n8.x4.trans.shared.b16 {%0,%1,%2,%3}, [%4];"
                 : "=r"(r0), "=r"(r1), "=r"(r2), "=r"(r3) : "r"(addr));
}

// ---------------------------------------------------------------------------
// Shared-memory layouts (union'd in the fused kernel)
// ---------------------------------------------------------------------------
struct ProjSmem {
    __half As[2][64][40];     // 10240 B
    __half Bsm[2][32][136];   // 17408 B
};
struct ScoreSmem {
    uint32_t Qh[32][36];      // 4608 B
    uint32_t Kt[32][33];      // 4224 B
    uint32_t Wsh[32];         // 128 B
};

// ---------------------------------------------------------------------------
// Convert the 6 fp32 operand arrays to fp16 once. Grid (384, 6), 256 thr.
// ---------------------------------------------------------------------------
__global__ __launch_bounds__(256) void cvt_kernel(
    const float* __restrict__ xq, const float* __restrict__ xk, const float* __restrict__ xv,
    const float* __restrict__ Wq, const float* __restrict__ Wk, const float* __restrict__ Wv)
{
    const int id = blockIdx.y;
    const float* src;
    __half* dst;
    int n;
    if (id < 3) {
        src = (id == 0) ? xq : (id == 1) ? xk : xv;
        dst = g_xh[id];
        n = BB * LQ * DD;
    } else {
        src = (id == 3) ? Wq : (id == 4) ? Wk : Wv;
        dst = g_wh[id - 3];
        n = DD * DD;
    }
    const int idx = (blockIdx.x * 256 + threadIdx.x) * 8;
    if (idx >= n) return;
    float4 a = *(const float4*)(src + idx);
    float4 b = *(const float4*)(src + idx + 4);
    __half2 h0 = __floats2half2_rn(a.x, a.y);
    __half2 h1 = __floats2half2_rn(a.z, a.w);
    __half2 h2 = __floats2half2_rn(b.x, b.y);
    __half2 h3 = __floats2half2_rn(b.z, b.w);
    uint4 o;
    o.x = *(const uint32_t*)&h0;
    o.y = *(const uint32_t*)&h1;
    o.z = *(const uint32_t*)&h2;
    o.w = *(const uint32_t*)&h3;
    *(uint4*)(dst + idx) = o;
}

// ---------------------------------------------------------------------------
// One 64(M)x128(N) fp16-mma projection tile (R13-proven body).
// ---------------------------------------------------------------------------
__device__ __forceinline__ void proj_tile(
    const __half* __restrict__ X, const __half* __restrict__ W,
    const float* __restrict__ bias, __half* __restrict__ Out,
    int m0, int n0, int t, ProjSmem& S)
{
    const int wid  = t >> 5;
    const int lane = t & 31;
    const int wm   = wid & 1;
    const int wn   = wid >> 1;
    const int grp  = lane >> 2;
    const int tig  = lane & 3;

    float acc[2][4][4];
    #pragma unroll
    for (int i = 0; i < 2; i++)
        #pragma unroll
        for (int j = 0; j < 4; j++)
            #pragma unroll
            for (int r = 0; r < 4; r++) acc[i][j][r] = 0.f;

    const int ar = t >> 2, acs = (t & 3) * 8;
    const int br = t >> 3, bcs = (t & 7) * 16;

    const __half* Xp = X + (size_t)(m0 + ar) * DD + acs;
    const __half* Wp = W + (size_t)br * DD + n0 + bcs;

    const int lrow = lane & 15;
    const int lca  = (lane >> 4) * 8;
    const uint32_t a_addr0 =
        (uint32_t)__cvta_generic_to_shared(&S.As[0][wm*32 + lrow][lca]);
    const int brow = ((lane >> 3) & 1) * 8 + (lane & 7);
    const int bcol = (lane >> 4) * 8;
    const uint32_t b_addr0 =
        (uint32_t)__cvta_generic_to_shared(&S.Bsm[0][brow][wn*32 + bcol]);

    __pipeline_memcpy_async(&S.As[0][ar][acs], Xp, 16);
    __pipeline_memcpy_async(&S.Bsm[0][br][bcs],     Wp,     16);
    __pipeline_memcpy_async(&S.Bsm[0][br][bcs + 8], Wp + 8, 16);
    __pipeline_commit();

    for (int k0 = 0; k0 < DD; k0 += 32) {
        const int buf = (k0 >> 5) & 1;
        if (k0 + 32 < DD) {
            const int nb = buf ^ 1;
            __pipeline_memcpy_async(&S.As[nb][ar][acs], Xp + k0 + 32, 16);
            const __half* wpn = Wp + (size_t)(k0 + 32) * DD;
            __pipeline_memcpy_async(&S.Bsm[nb][br][bcs],     wpn,     16);
            __pipeline_memcpy_async(&S.Bsm[nb][br][bcs + 8], wpn + 8, 16);
            __pipeline_commit();
            __pipeline_wait_prior(1);
        } else {
            __pipeline_wait_prior(0);
        }
        __syncthreads();

        #pragma unroll
        for (int ks = 0; ks < 2; ks++) {
            uint32_t a[2][4];
            #pragma unroll
            for (int mi = 0; mi < 2; mi++) {
                const uint32_t ad = a_addr0 + (uint32_t)(buf*5120 + mi*1280 + ks*32);
                ldsm_x4(a[mi][0], a[mi][1], a[mi][2], a[mi][3], ad);
            }
            uint32_t b[4][2];
            #pragma unroll
            for (int p = 0; p < 2; p++) {
                const uint32_t bd = b_addr0 + (uint32_t)(buf*8704 + ks*4352 + p*32);
                ldsm_x4_t(b[p*2][0], b[p*2][1], b[p*2+1][0], b[p*2+1][1], bd);
            }
            #pragma unroll
            for (int mi = 0; mi < 2; mi++)
                #pragma unroll
                for (int ni = 0; ni < 4; ni++)
                    mma_f16(acc[mi][ni][0], acc[mi][ni][1], acc[mi][ni][2], acc[mi][ni][3],
                            a[mi][0], a[mi][1], a[mi][2], a[mi][3],
                            b[ni][0], b[ni][1]);
        }
        __syncthreads();
    }

    #pragma unroll
    for (int mi = 0; mi < 2; mi++) {
        #pragma unroll
        for (int ni = 0; ni < 4; ni++) {
            const int col = n0 + wn*32 + ni*8 + 2*tig;
            const float b0 = bias[col], b1 = bias[col+1];
            const int r0 = m0 + wm*32 + mi*16 + grp;
            const int r1 = r0 + 8;
            __half2 lo = __floats2half2_rn(acc[mi][ni][0] + b0, acc[mi][ni][1] + b1);
            __half2 hi = __floats2half2_rn(acc[mi][ni][2] + b0, acc[mi][ni][3] + b1);
            *(__half2*)&Out[(size_t)r0 * DD + col] = lo;
            *(__half2*)&Out[(size_t)r1 * DD + col] = hi;
        }
    }
}

// ---------------------------------------------------------------------------
// One 32q x 32k score tile via tanh.approx.f16x2 (R13-proven body).
// fp16 HFMA2 partials over 4 d-pairs, flushed to fp32.
// ---------------------------------------------------------------------------
__device__ __forceinline__ void score_tile(
    const float* __restrict__ Ws, float bsv,
    int bz, int q0, int k0, int t, ScoreSmem& S)
{
    const int tx = t & 15, ty = t >> 4;

    float acc00 = 0.f, acc01 = 0.f, acc10 = 0.f, acc11 = 0.f;

    const __half* qb = g_qh + ((size_t)bz*LQ + q0) * DD;
    const __half* kb = g_kh + ((size_t)bz*LK + k0) * DD;

    const int lr = t >> 3;          // 0..31
    const int lc = t & 7;           // 0..7  (8 halves = 16B per thread)

    for (int d0 = 0; d0 < DD; d0 += 64) {
        uint4 qv = *(const uint4*)(qb + (size_t)lr*DD + d0 + lc*8);
        *(uint4*)&S.Qh[lr][lc*4] = qv;
        uint4 kv = *(const uint4*)(kb + (size_t)lr*DD + d0 + lc*8);
        S.Kt[lc*4+0][lr] = kv.x;
        S.Kt[lc*4+1][lr] = kv.y;
        S.Kt[lc*4+2][lr] = kv.z;
        S.Kt[lc*4+3][lr] = kv.w;
        if (t < 32) {
            float2 w = *(const float2*)&Ws[d0 + t*2];
            __half2 wh = __floats2half2_rn(w.x, w.y);
            S.Wsh[t] = *(const uint32_t*)&wh;
        }
        __syncthreads();

        #pragma unroll
        for (int g = 0; g < 8; g++) {
            uint32_t p00 = 0u, p01 = 0u, p10 = 0u, p11 = 0u;
            #pragma unroll
            for (int u = 0; u < 4; u++) {
                const int dp = g*4 + u;
                const uint32_t w2 = S.Wsh[dp];
                const uint32_t qa = S.Qh[ty*2+0][dp];
                const uint32_t qc = S.Qh[ty*2+1][dp];
                const uint32_t ka = S.Kt[dp][tx*2+0];
                const uint32_t kc = S.Kt[dp][tx*2+1];
                p00 = hfma2u(w2, tanh2u(hadd2u(qa, ka)), p00);
                p01 = hfma2u(w2, tanh2u(hadd2u(qa, kc)), p01);
                p10 = hfma2u(w2, tanh2u(hadd2u(qc, ka)), p10);
                p11 = hfma2u(w2, tanh2u(hadd2u(qc, kc)), p11);
            }
            float2 f0 = h22f2(p00); acc00 += f0.x + f0.y;
            float2 f1 = h22f2(p01); acc01 += f1.x + f1.y;
            float2 f2 = h22f2(p10); acc10 += f2.x + f2.y;
            float2 f3 = h22f2(p11); acc11 += f3.x + f3.y;
        }
        __syncthreads();
    }

    float* sp = g_scores + ((size_t)bz*LQ + q0) * LK + k0;
    sp[(ty*2+0)*LK + tx*2+0] = acc00 + bsv;
    sp[(ty*2+0)*LK + tx*2+1] = acc01 + bsv;
    sp[(ty*2+1)*LK + tx*2+0] = acc10 + bsv;
    sp[(ty*2+1)*LK + tx*2+1] = acc11 + bsv;
}

// ---------------------------------------------------------------------------
// q,k projections. Grid (6, 16, 2).
// ---------------------------------------------------------------------------
__global__ __launch_bounds__(256) void proj_qk_kernel(
    const float* __restrict__ bq, const float* __restrict__ bk)
{
    __shared__ ProjSmem S;
    const int z = blockIdx.z;
    proj_tile(g_xh[z], g_wh[z], (z == 0) ? bq : bk, (z == 0) ? g_qh : g_kh,
              blockIdx.y * 64, blockIdx.x * 128, threadIdx.x, S);
}

// ---------------------------------------------------------------------------
// Fused: blocks [0,96) = v-projection tiles (tensor pipe, scheduled FIRST so
// they run inside wave 1), blocks [96,352) = score tiles (MUFU pipe).
// Independent work; proj_v's ~8us hides under score's ~41us MUFU time.
// ---------------------------------------------------------------------------
__global__ __launch_bounds__(256) void fused_score_projv_kernel(
    const float* __restrict__ bv,
    const float* __restrict__ Ws, const float* __restrict__ bsp)
{
    __shared__ union { ProjSmem pv; ScoreSmem sc; } S;
    const int bid = blockIdx.x;
    const int t   = threadIdx.x;

    if (bid < 96) {
        // v-projection tile: 96 = 6 n x 16 m
        const int n0 = (bid % 6) * 128;
        const int m0 = (bid / 6) * 64;
        proj_tile(g_xh[2], g_wh[2], bv, g_vh, m0, n0, t, S.pv);
    } else {
        // score tile: bz (4) x q0 (8) x k0 (8)
        const int sid = bid - 96;
        const int bz  = sid >> 6;
        const int rem = sid & 63;
        const int q0  = (rem >> 3) * 32;
        const int k0  = (rem & 7) * 32;
        score_tile(Ws, *bsp, bz, q0, k0, t, S.sc);
    }
}

// ---------------------------------------------------------------------------
// Row softmax over LK=256. One block (256 threads) per (b,q) row.
// ---------------------------------------------------------------------------
__global__ __launch_bounds__(256) void softmax_kernel(float* __restrict__ wout)
{
    const int row = blockIdx.x;
    const int t   = threadIdx.x;
    __shared__ float red[8];

    const float v = g_scores[(size_t)row*LK + t];

    float m = v;
    #pragma unroll
    for (int o = 16; o > 0; o >>= 1) m = fmaxf(m, __shfl_xor_sync(0xffffffffu, m, o));
    if ((t & 31) == 0) red[t >> 5] = m;
    __syncthreads();
    float mx = red[0];
    #pragma unroll
    for (int i = 1; i < 8; i++) mx = fmaxf(mx, red[i]);
    __syncthreads();

    const float e = __expf(v - mx);
    float s = e;
    #pragma unroll
    for (int o = 16; o > 0; o >>= 1) s += __shfl_xor_sync(0xffffffffu, s, o);
    if ((t & 31) == 0) red[t >> 5] = s;
    __syncthreads();
    float sum = 0.f;
    #pragma unroll
    for (int i = 0; i < 8; i++) sum += red[i];

    wout[(size_t)row*LK + t] = e * (1.0f / sum);
}

// ---------------------------------------------------------------------------
// attended = weights @ v via fp16 mma (unchanged R13, ~13us).
// ---------------------------------------------------------------------------
__global__ __launch_bounds__(256) void av_kernel(const float* __restrict__ wts,
                                                 float* __restrict__ out)
{
    const int b  = blockIdx.z;
    const int q0 = blockIdx.y * 32;
    const int d0 = blockIdx.x * 128;

    __shared__ __half As[2][32][40];
    __shared__ __half Bsm[2][32][136];

    const int t    = threadIdx.x;
    const int wid  = t >> 5;
    const int lane = t & 31;
    const int grp  = lane >> 2;
    const int tig  = lane & 3;

    float acc[2][2][4];
    #pragma unroll
    for (int i = 0; i < 2; i++)
        #pragma unroll
        for (int j = 0; j < 2; j++)
            #pragma unroll
            for (int r = 0; r < 4; r++) acc[i][j][r] = 0.f;

    const int ar = t >> 3, ac4 = (t & 7) * 4;
    const int br = t >> 3, bcs = (t & 7) * 16;

    const float*  Ap = wts + ((size_t)b*LQ + q0 + ar) * LK + ac4;
    const __half* Bp = g_vh + ((size_t)b*LK + br) * DD + d0 + bcs;

    const int lrow = lane & 15;
    const int lca  = (lane >> 4) * 8;
    const uint32_t a_addr0 = (uint32_t)__cvta_generic_to_shared(&As[0][lrow][lca]);
    const int brow = ((lane >> 3) & 1) * 8 + (lane & 7);
    const int bcol = (lane >> 4) * 8;
    const uint32_t b_addr0 =
        (uint32_t)__cvta_generic_to_shared(&Bsm[0][brow][wid*16 + bcol]);

    float4 pa = *(const float4*)(Ap);
    __pipeline_memcpy_async(&Bsm[0][br][bcs],     Bp,     16);
    __pipeline_memcpy_async(&Bsm[0][br][bcs + 8], Bp + 8, 16);
    __pipeline_commit();

    for (int j0 = 0; j0 < LK; j0 += 32) {
        const int buf = (j0 >> 5) & 1;
        {
            __half2 h0 = __floats2half2_rn(pa.x, pa.y);
            __half2 h1 = __floats2half2_rn(pa.z, pa.w);
            uint2 o = { *(const uint32_t*)&h0, *(const uint32_t*)&h1 };
            *(uint2*)&As[buf][ar][ac4] = o;
        }
        if (j0 + 32 < LK) {
            const int nb = buf ^ 1;
            pa = *(const float4*)(Ap + j0 + 32);
            const __half* bpn = Bp + (size_t)(j0 + 32) * DD;
            __pipeline_memcpy_async(&Bsm[nb][br][bcs],     bpn,     16);
            __pipeline_memcpy_async(&Bsm[nb][br][bcs + 8], bpn + 8, 16);
            __pipeline_commit();
            __pipeline_wait_prior(1);
        } else {
            __pipeline_wait_prior(0);
        }
        __syncthreads();

        #pragma unroll
        for (int ks = 0; ks < 2; ks++) {
            uint32_t a[2][4];
            #pragma unroll
            for (int mi = 0; mi < 2; mi++) {
                const uint32_t ad = a_addr0 + (uint32_t)(buf*2560 + mi*1280 + ks*32);
                ldsm_x4(a[mi][0], a[mi][1], a[mi][2], a[mi][3], ad);
            }
            uint32_t bf[2][2];
            {
                const uint32_t bd = b_addr0 + (uint32_t)(buf*8704 + ks*4352);
                ldsm_x4_t(bf[0][0], bf[0][1], bf[1][0], bf[1][1], bd);
            }
            #pragma unroll
            for (int mi = 0; mi < 2; mi++)
                #pragma unroll
                for (int ni = 0; ni < 2; ni++)
                    mma_f16(acc[mi][ni][0], acc[mi][ni][1], acc[mi][ni][2], acc[mi][ni][3],
                            a[mi][0], a[mi][1], a[mi][2], a[mi][3],
                            bf[ni][0], bf[ni][1]);
        }
        __syncthreads();
    }

    #pragma unroll
    for (int mi = 0; mi < 2; mi++) {
        #pragma unroll
        for (int ni = 0; ni < 2; ni++) {
            const int col = d0 + wid*16 + ni*8 + 2*tig;
            const int r0  = q0 + mi*16 + grp;
            const int r1  = r0 + 8;
            float2 lo = { acc[mi][ni][0], acc[mi][ni][1] };
            float2 hi = { acc[mi][ni][2], acc[mi][ni][3] };
            *(float2*)&out[((size_t)b*LQ + r0) * DD + col] = lo;
            *(float2*)&out[((size_t)b*LQ + r1) * DD + col] = hi;
        }
    }
}

// ---------------------------------------------------------------------------
extern "C" void kernel_launch(void* const* d_in, const int* in_sizes, int n_in,
                              void* d_out, int out_size)
{
    const float* query = (const float*)d_in[0];
    const float* key   = (const float*)d_in[1];
    const float* value = (const float*)d_in[2];
    const float* Wq    = (const float*)d_in[3];
    const float* bq    = (const float*)d_in[4];
    const float* Wk    = (const float*)d_in[5];
    const float* bk    = (const float*)d_in[6];
    const float* Wv    = (const float*)d_in[7];
    const float* bv    = (const float*)d_in[8];
    const float* Ws    = (const float*)d_in[9];
    const float* bs    = (const float*)d_in[10];

    float* att = (float*)d_out;                  // [B,LQ,D]
    float* wts = att + (size_t)BB * LQ * DD;     // [B,LQ,LK]

    // 0) fp32 -> fp16 operand conversion (once)
    cvt_kernel<<<dim3(384, 6), 256>>>(query, key, value, Wq, Wk, Wv);

    // 1) q,k projections only (v deferred into the fused kernel)
    proj_qk_kernel<<<dim3(DD/128, (BB*LQ)/64, 2), 256>>>(bq, bk);

    // 2) v-projection (tensor) overlapped under score (MUFU); projv first
    fused_score_projv_kernel<<<96 + 256, 256>>>(bv, Ws, bs);

    // 3) softmax -> attention_weights into d_out
    softmax_kernel<<<BB*LQ, 256>>>(wts);

    // 4) attended = weights @ v (fp16 mma)
    av_kernel<<<dim3(DD/128, LQ/32, BB), 256>>>(wts, att);
}

// round 16
// speedup vs baseline: 1.2133x; 1.2126x over previous
#include <cuda_runtime.h>
#include <cuda_fp16.h>
#include <cuda_pipeline.h>
#include <cstdint>

#define BB 4
#define LQ 256
#define LK 256
#define DD 768

// Scratch (no cudaMalloc allowed)
__device__ __half g_qh[BB*LQ*DD];        // q projection (fp16, feeds score)
__device__ __half g_kh[BB*LK*DD];        // k projection (fp16, feeds score)
__device__ __half g_vh[BB*LK*DD];        // v projection (fp16, feeds av)
__device__ __half g_xh[3][BB*LQ*DD];     // fp16 copies of query,key,value inputs
__device__ __half g_wh[3][DD*DD];        // fp16 copies of Wq,Wk,Wv
__device__ float  g_scores[BB*LQ*LK];

// ---- f16x2 helpers ----
__device__ __forceinline__ uint32_t hadd2u(uint32_t a, uint32_t b) {
    uint32_t r;
    asm("add.rn.f16x2 %0, %1, %2;" : "=r"(r) : "r"(a), "r"(b));
    return r;
}
__device__ __forceinline__ uint32_t tanh2u(uint32_t a) {
    uint32_t r;
    asm("tanh.approx.f16x2 %0, %1;" : "=r"(r) : "r"(a));
    return r;
}
__device__ __forceinline__ uint32_t hfma2u(uint32_t a, uint32_t b, uint32_t c) {
    uint32_t r;
    asm("fma.rn.f16x2 %0, %1, %2, %3;" : "=r"(r) : "r"(a), "r"(b), "r"(c));
    return r;
}
__device__ __forceinline__ float2 h22f2(uint32_t h) {
    __half2 hh = *(__half2*)&h;
    return __half22float2(hh);
}

// ---- fp16 mma helpers ----
__device__ __forceinline__ void mma_f16(float& d0, float& d1, float& d2, float& d3,
                                        uint32_t a0, uint32_t a1, uint32_t a2, uint32_t a3,
                                        uint32_t b0, uint32_t b1) {
    asm("mma.sync.aligned.m16n8k16.row.col.f32.f16.f16.f32 "
        "{%0,%1,%2,%3}, {%4,%5,%6,%7}, {%8,%9}, {%0,%1,%2,%3};"
        : "+f"(d0), "+f"(d1), "+f"(d2), "+f"(d3)
        : "r"(a0), "r"(a1), "r"(a2), "r"(a3), "r"(b0), "r"(b1));
}
__device__ __forceinline__ void ldsm_x4(uint32_t& r0, uint32_t& r1, uint32_t& r2, uint32_t& r3,
                                        uint32_t addr) {
    asm volatile("ldmatrix.sync.aligned.m8n8.x4.shared.b16 {%0,%1,%2,%3}, [%4];"
                 : "=r"(r0), "=r"(r1), "=r"(r2), "=r"(r3) : "r"(addr));
}
__device__ __forceinline__ void ldsm_x4_t(uint32_t& r0, uint32_t& r1, uint32_t& r2, uint32_t& r3,
                                          uint32_t addr) {
    asm volatile("ldmatrix.sync.aligned.m8n8.x4.trans.shared.b16 {%0,%1,%2,%3}, [%4];"
                 : "=r"(r0), "=r"(r1), "=r"(r2), "=r"(r3) : "r"(addr));
}

// ---------------------------------------------------------------------------
// Shared-memory layouts
// ---------------------------------------------------------------------------
struct ProjSmem {
    __half As[2][64][40];
    __half Bsm[2][32][136];
};
struct ScoreSmem {
    uint32_t Qh[32][36];
    uint32_t Kt[32][33];
    uint32_t Wsh[32];
};

// ---------------------------------------------------------------------------
// fp32 -> fp16 conversion helper
// ---------------------------------------------------------------------------
__device__ __forceinline__ void cvt_one(const float* __restrict__ src,
                                        __half* __restrict__ dst, int n,
                                        int bx, int t)
{
    const int idx = (bx * 256 + t) * 8;
    if (idx >= n) return;
    float4 a = *(const float4*)(src + idx);
    float4 b = *(const float4*)(src + idx + 4);
    __half2 h0 = __floats2half2_rn(a.x, a.y);
    __half2 h1 = __floats2half2_rn(a.z, a.w);
    __half2 h2 = __floats2half2_rn(b.x, b.y);
    __half2 h3 = __floats2half2_rn(b.z, b.w);
    uint4 o;
    o.x = *(const uint32_t*)&h0;
    o.y = *(const uint32_t*)&h1;
    o.z = *(const uint32_t*)&h2;
    o.w = *(const uint32_t*)&h3;
    *(uint4*)(dst + idx) = o;
}

// cvt for q,k inputs + Wq,Wk. Grid (384, 4).
__global__ __launch_bounds__(256) void cvt_main_kernel(
    const float* __restrict__ xq, const float* __restrict__ xk,
    const float* __restrict__ Wq, const float* __restrict__ Wk)
{
    const int id = blockIdx.y;
    if (id == 0)      cvt_one(xq, g_xh[0], BB*LQ*DD, blockIdx.x, threadIdx.x);
    else if (id == 1) cvt_one(xk, g_xh[1], BB*LQ*DD, blockIdx.x, threadIdx.x);
    else if (id == 2) cvt_one(Wq, g_wh[0], DD*DD,    blockIdx.x, threadIdx.x);
    else              cvt_one(Wk, g_wh[1], DD*DD,    blockIdx.x, threadIdx.x);
}

// cvt for v input + Wv (side stream). Grid (384, 2).
__global__ __launch_bounds__(256) void cvt_v_kernel(
    const float* __restrict__ xv, const float* __restrict__ Wv)
{
    if (blockIdx.y == 0) cvt_one(xv, g_xh[2], BB*LQ*DD, blockIdx.x, threadIdx.x);
    else                 cvt_one(Wv, g_wh[2], DD*DD,    blockIdx.x, threadIdx.x);
}

// ---------------------------------------------------------------------------
// One 64(M)x128(N) fp16-mma projection tile (R13-proven body).
// ---------------------------------------------------------------------------
__device__ __forceinline__ void proj_tile(
    const __half* __restrict__ X, const __half* __restrict__ W,
    const float* __restrict__ bias, __half* __restrict__ Out,
    int m0, int n0, int t, ProjSmem& S)
{
    const int wid  = t >> 5;
    const int lane = t & 31;
    const int wm   = wid & 1;
    const int wn   = wid >> 1;
    const int grp  = lane >> 2;
    const int tig  = lane & 3;

    float acc[2][4][4];
    #pragma unroll
    for (int i = 0; i < 2; i++)
        #pragma unroll
        for (int j = 0; j < 4; j++)
            #pragma unroll
            for (int r = 0; r < 4; r++) acc[i][j][r] = 0.f;

    const int ar = t >> 2, acs = (t & 3) * 8;
    const int br = t >> 3, bcs = (t & 7) * 16;

    const __half* Xp = X + (size_t)(m0 + ar) * DD + acs;
    const __half* Wp = W + (size_t)br * DD + n0 + bcs;

    const int lrow = lane & 15;
    const int lca  = (lane >> 4) * 8;
    const uint32_t a_addr0 =
        (uint32_t)__cvta_generic_to_shared(&S.As[0][wm*32 + lrow][lca]);
    const int brow = ((lane >> 3) & 1) * 8 + (lane & 7);
    const int bcol = (lane >> 4) * 8;
    const uint32_t b_addr0 =
        (uint32_t)__cvta_generic_to_shared(&S.Bsm[0][brow][wn*32 + bcol]);

    __pipeline_memcpy_async(&S.As[0][ar][acs], Xp, 16);
    __pipeline_memcpy_async(&S.Bsm[0][br][bcs],     Wp,     16);
    __pipeline_memcpy_async(&S.Bsm[0][br][bcs + 8], Wp + 8, 16);
    __pipeline_commit();

    for (int k0 = 0; k0 < DD; k0 += 32) {
        const int buf = (k0 >> 5) & 1;
        if (k0 + 32 < DD) {
            const int nb = buf ^ 1;
            __pipeline_memcpy_async(&S.As[nb][ar][acs], Xp + k0 + 32, 16);
            const __half* wpn = Wp + (size_t)(k0 + 32) * DD;
            __pipeline_memcpy_async(&S.Bsm[nb][br][bcs],     wpn,     16);
            __pipeline_memcpy_async(&S.Bsm[nb][br][bcs + 8], wpn + 8, 16);
            __pipeline_commit();
            __pipeline_wait_prior(1);
        } else {
            __pipeline_wait_prior(0);
        }
        __syncthreads();

        #pragma unroll
        for (int ks = 0; ks < 2; ks++) {
            uint32_t a[2][4];
            #pragma unroll
            for (int mi = 0; mi < 2; mi++) {
                const uint32_t ad = a_addr0 + (uint32_t)(buf*5120 + mi*1280 + ks*32);
                ldsm_x4(a[mi][0], a[mi][1], a[mi][2], a[mi][3], ad);
            }
            uint32_t b[4][2];
            #pragma unroll
            for (int p = 0; p < 2; p++) {
                const uint32_t bd = b_addr0 + (uint32_t)(buf*8704 + ks*4352 + p*32);
                ldsm_x4_t(b[p*2][0], b[p*2][1], b[p*2+1][0], b[p*2+1][1], bd);
            }
            #pragma unroll
            for (int mi = 0; mi < 2; mi++)
                #pragma unroll
                for (int ni = 0; ni < 4; ni++)
                    mma_f16(acc[mi][ni][0], acc[mi][ni][1], acc[mi][ni][2], acc[mi][ni][3],
                            a[mi][0], a[mi][1], a[mi][2], a[mi][3],
                            b[ni][0], b[ni][1]);
        }
        __syncthreads();
    }

    #pragma unroll
    for (int mi = 0; mi < 2; mi++) {
        #pragma unroll
        for (int ni = 0; ni < 4; ni++) {
            const int col = n0 + wn*32 + ni*8 + 2*tig;
            const float b0 = bias[col], b1 = bias[col+1];
            const int r0 = m0 + wm*32 + mi*16 + grp;
            const int r1 = r0 + 8;
            __half2 lo = __floats2half2_rn(acc[mi][ni][0] + b0, acc[mi][ni][1] + b1);
            __half2 hi = __floats2half2_rn(acc[mi][ni][2] + b0, acc[mi][ni][3] + b1);
            *(__half2*)&Out[(size_t)r0 * DD + col] = lo;
            *(__half2*)&Out[(size_t)r1 * DD + col] = hi;
        }
    }
}

// q,k projections. Grid (6, 16, 2).
__global__ __launch_bounds__(256) void proj_qk_kernel(
    const float* __restrict__ bq, const float* __restrict__ bk)
{
    __shared__ ProjSmem S;
    const int z = blockIdx.z;
    proj_tile(g_xh[z], g_wh[z], (z == 0) ? bq : bk, (z == 0) ? g_qh : g_kh,
              blockIdx.y * 64, blockIdx.x * 128, threadIdx.x, S);
}

// v projection (side stream). Grid (6, 16).
__global__ __launch_bounds__(256) void proj_v_kernel(const float* __restrict__ bv)
{
    __shared__ ProjSmem S;
    proj_tile(g_xh[2], g_wh[2], bv, g_vh,
              blockIdx.y * 64, blockIdx.x * 128, threadIdx.x, S);
}

// ---------------------------------------------------------------------------
// Scores via tanh.approx.f16x2 (R13-proven, ~40.6us). 32x32 tile, 256 thr.
// Grid (8,8,4).
// ---------------------------------------------------------------------------
__global__ __launch_bounds__(256) void score_kernel(const float* __restrict__ Ws,
                                                    const float* __restrict__ bsp)
{
    __shared__ ScoreSmem S;
    const int bz = blockIdx.z;
    const int q0 = blockIdx.y * 32;
    const int k0 = blockIdx.x * 32;

    const int t  = threadIdx.x;
    const int tx = t & 15, ty = t >> 4;

    float acc00 = 0.f, acc01 = 0.f, acc10 = 0.f, acc11 = 0.f;

    const __half* qb = g_qh + ((size_t)bz*LQ + q0) * DD;
    const __half* kb = g_kh + ((size_t)bz*LK + k0) * DD;

    const int lr = t >> 3;
    const int lc = t & 7;

    for (int d0 = 0; d0 < DD; d0 += 64) {
        uint4 qv = *(const uint4*)(qb + (size_t)lr*DD + d0 + lc*8);
        *(uint4*)&S.Qh[lr][lc*4] = qv;
        uint4 kv = *(const uint4*)(kb + (size_t)lr*DD + d0 + lc*8);
        S.Kt[lc*4+0][lr] = kv.x;
        S.Kt[lc*4+1][lr] = kv.y;
        S.Kt[lc*4+2][lr] = kv.z;
        S.Kt[lc*4+3][lr] = kv.w;
        if (t < 32) {
            float2 w = *(const float2*)&Ws[d0 + t*2];
            __half2 wh = __floats2half2_rn(w.x, w.y);
            S.Wsh[t] = *(const uint32_t*)&wh;
        }
        __syncthreads();

        #pragma unroll
        for (int g = 0; g < 8; g++) {
            uint32_t p00 = 0u, p01 = 0u, p10 = 0u, p11 = 0u;
            #pragma unroll
            for (int u = 0; u < 4; u++) {
                const int dp = g*4 + u;
                const uint32_t w2 = S.Wsh[dp];
                const uint32_t qa = S.Qh[ty*2+0][dp];
                const uint32_t qc = S.Qh[ty*2+1][dp];
                const uint32_t ka = S.Kt[dp][tx*2+0];
                const uint32_t kc = S.Kt[dp][tx*2+1];
                p00 = hfma2u(w2, tanh2u(hadd2u(qa, ka)), p00);
                p01 = hfma2u(w2, tanh2u(hadd2u(qa, kc)), p01);
                p10 = hfma2u(w2, tanh2u(hadd2u(qc, ka)), p10);
                p11 = hfma2u(w2, tanh2u(hadd2u(qc, kc)), p11);
            }
            float2 f0 = h22f2(p00); acc00 += f0.x + f0.y;
            float2 f1 = h22f2(p01); acc01 += f1.x + f1.y;
            float2 f2 = h22f2(p10); acc10 += f2.x + f2.y;
            float2 f3 = h22f2(p11); acc11 += f3.x + f3.y;
        }
        __syncthreads();
    }

    const float bsv = *bsp;
    float* sp = g_scores + ((size_t)bz*LQ + q0) * LK + k0;
    sp[(ty*2+0)*LK + tx*2+0] = acc00 + bsv;
    sp[(ty*2+0)*LK + tx*2+1] = acc01 + bsv;
    sp[(ty*2+1)*LK + tx*2+0] = acc10 + bsv;
    sp[(ty*2+1)*LK + tx*2+1] = acc11 + bsv;
}

// ---------------------------------------------------------------------------
// Row softmax over LK=256. One block (256 threads) per (b,q) row.
// ---------------------------------------------------------------------------
__global__ __launch_bounds__(256) void softmax_kernel(float* __restrict__ wout)
{
    const int row = blockIdx.x;
    const int t   = threadIdx.x;
    __shared__ float red[8];

    const float v = g_scores[(size_t)row*LK + t];

    float m = v;
    #pragma unroll
    for (int o = 16; o > 0; o >>= 1) m = fmaxf(m, __shfl_xor_sync(0xffffffffu, m, o));
    if ((t & 31) == 0) red[t >> 5] = m;
    __syncthreads();
    float mx = red[0];
    #pragma unroll
    for (int i = 1; i < 8; i++) mx = fmaxf(mx, red[i]);
    __syncthreads();

    const float e = __expf(v - mx);
    float s = e;
    #pragma unroll
    for (int o = 16; o > 0; o >>= 1) s += __shfl_xor_sync(0xffffffffu, s, o);
    if ((t & 31) == 0) red[t >> 5] = s;
    __syncthreads();
    float sum = 0.f;
    #pragma unroll
    for (int i = 0; i < 8; i++) sum += red[i];

    wout[(size_t)row*LK + t] = e * (1.0f / sum);
}

// ---------------------------------------------------------------------------
// attended = weights @ v via fp16 mma (R13-proven, ~13us). Grid (6,8,4).
// ---------------------------------------------------------------------------
__global__ __launch_bounds__(256) void av_kernel(const float* __restrict__ wts,
                                                 float* __restrict__ out)
{
    const int b  = blockIdx.z;
    const int q0 = blockIdx.y * 32;
    const int d0 = blockIdx.x * 128;

    __shared__ __half As[2][32][40];
    __shared__ __half Bsm[2][32][136];

    const int t    = threadIdx.x;
    const int wid  = t >> 5;
    const int lane = t & 31;
    const int grp  = lane >> 2;
    const int tig  = lane & 3;

    float acc[2][2][4];
    #pragma unroll
    for (int i = 0; i < 2; i++)
        #pragma unroll
        for (int j = 0; j < 2; j++)
            #pragma unroll
            for (int r = 0; r < 4; r++) acc[i][j][r] = 0.f;

    const int ar = t >> 3, ac4 = (t & 7) * 4;
    const int br = t >> 3, bcs = (t & 7) * 16;

    const float*  Ap = wts + ((size_t)b*LQ + q0 + ar) * LK + ac4;
    const __half* Bp = g_vh + ((size_t)b*LK + br) * DD + d0 + bcs;

    const int lrow = lane & 15;
    const int lca  = (lane >> 4) * 8;
    const uint32_t a_addr0 = (uint32_t)__cvta_generic_to_shared(&As[0][lrow][lca]);
    const int brow = ((lane >> 3) & 1) * 8 + (lane & 7);
    const int bcol = (lane >> 4) * 8;
    const uint32_t b_addr0 =
        (uint32_t)__cvta_generic_to_shared(&Bsm[0][brow][wid*16 + bcol]);

    float4 pa = *(const float4*)(Ap);
    __pipeline_memcpy_async(&Bsm[0][br][bcs],     Bp,     16);
    __pipeline_memcpy_async(&Bsm[0][br][bcs + 8], Bp + 8, 16);
    __pipeline_commit();

    for (int j0 = 0; j0 < LK; j0 += 32) {
        const int buf = (j0 >> 5) & 1;
        {
            __half2 h0 = __floats2half2_rn(pa.x, pa.y);
            __half2 h1 = __floats2half2_rn(pa.z, pa.w);
            uint2 o = { *(const uint32_t*)&h0, *(const uint32_t*)&h1 };
            *(uint2*)&As[buf][ar][ac4] = o;
        }
        if (j0 + 32 < LK) {
            const int nb = buf ^ 1;
            pa = *(const float4*)(Ap + j0 + 32);
            const __half* bpn = Bp + (size_t)(j0 + 32) * DD;
            __pipeline_memcpy_async(&Bsm[nb][br][bcs],     bpn,     16);
            __pipeline_memcpy_async(&Bsm[nb][br][bcs + 8], bpn + 8, 16);
            __pipeline_commit();
            __pipeline_wait_prior(1);
        } else {
            __pipeline_wait_prior(0);
        }
        __syncthreads();

        #pragma unroll
        for (int ks = 0; ks < 2; ks++) {
            uint32_t a[2][4];
            #pragma unroll
            for (int mi = 0; mi < 2; mi++) {
                const uint32_t ad = a_addr0 + (uint32_t)(buf*2560 + mi*1280 + ks*32);
                ldsm_x4(a[mi][0], a[mi][1], a[mi][2], a[mi][3], ad);
            }
            uint32_t bf[2][2];
            {
                const uint32_t bd = b_addr0 + (uint32_t)(buf*8704 + ks*4352);
                ldsm_x4_t(bf[0][0], bf[0][1], bf[1][0], bf[1][1], bd);
            }
            #pragma unroll
            for (int mi = 0; mi < 2; mi++)
                #pragma unroll
                for (int ni = 0; ni < 2; ni++)
                    mma_f16(acc[mi][ni][0], acc[mi][ni][1], acc[mi][ni][2], acc[mi][ni][3],
                            a[mi][0], a[mi][1], a[mi][2], a[mi][3],
                            bf[ni][0], bf[ni][1]);
        }
        __syncthreads();
    }

    #pragma unroll
    for (int mi = 0; mi < 2; mi++) {
        #pragma unroll
        for (int ni = 0; ni < 2; ni++) {
            const int col = d0 + wid*16 + ni*8 + 2*tig;
            const int r0  = q0 + mi*16 + grp;
            const int r1  = r0 + 8;
            float2 lo = { acc[mi][ni][0], acc[mi][ni][1] };
            float2 hi = { acc[mi][ni][2], acc[mi][ni][3] };
            *(float2*)&out[((size_t)b*LQ + r0) * DD + col] = lo;
            *(float2*)&out[((size_t)b*LQ + r1) * DD + col] = hi;
        }
    }
}

// ---------------------------------------------------------------------------
extern "C" void kernel_launch(void* const* d_in, const int* in_sizes, int n_in,
                              void* d_out, int out_size)
{
    const float* query = (const float*)d_in[0];
    const float* key   = (const float*)d_in[1];
    const float* value = (const float*)d_in[2];
    const float* Wq    = (const float*)d_in[3];
    const float* bq    = (const float*)d_in[4];
    const float* Wk    = (const float*)d_in[5];
    const float* bk    = (const float*)d_in[6];
    const float* Wv    = (const float*)d_in[7];
    const float* bv    = (const float*)d_in[8];
    const float* Ws    = (const float*)d_in[9];
    const float* bs    = (const float*)d_in[10];

    float* att = (float*)d_out;                  // [B,LQ,D]
    float* wts = att + (size_t)BB * LQ * DD;     // [B,LQ,LK]

    // side stream for the v-chain (fresh per call; not destroyed — destroying
    // a stream that is part of an active capture is illegal)
    cudaStream_t s2;
    cudaStreamCreateWithFlags(&s2, cudaStreamNonBlocking);
    cudaEvent_t evFork, evV;
    cudaEventCreateWithFlags(&evFork, cudaEventDisableTiming);
    cudaEventCreateWithFlags(&evV,   cudaEventDisableTiming);

    // fork: attach s2 to the capture graph
    cudaEventRecord(evFork, 0);
    cudaStreamWaitEvent(s2, evFork, 0);

    // side chain: cvt(v, Wv) -> proj_v  (tensor work, hides under score)
    cvt_v_kernel<<<dim3(384, 2), 256, 0, s2>>>(value, Wv);
    proj_v_kernel<<<dim3(DD/128, (BB*LQ)/64), 256, 0, s2>>>(bv);
    cudaEventRecord(evV, s2);

    // main chain: cvt(q,k,Wq,Wk) -> proj_qk -> score -> softmax
    cvt_main_kernel<<<dim3(384, 4), 256>>>(query, key, Wq, Wk);
    proj_qk_kernel<<<dim3(DD/128, (BB*LQ)/64, 2), 256>>>(bq, bk);
    score_kernel<<<dim3(LK/32, LQ/32, BB), 256>>>(Ws, bs);
    softmax_kernel<<<BB*LQ, 256>>>(wts);

    // join: av needs proj_v (side) + softmax (main)
    cudaStreamWaitEvent(0, evV, 0);
    av_kernel<<<dim3(DD/128, LQ/32, BB), 256>>>(wts, att);
}